// round 1
// baseline (speedup 1.0000x reference)
#include <cuda_runtime.h>

#define Bb    2
#define NSEQ  8192
#define DIMV  512
#define NH    8
#define BHn   16
#define DHd   64
#define MLM   256
#define LGRP  32
#define KSZ   33
#define PADc  16
#define SCALE 0.125f
#define NCHUNK 32

// ---------------- static device scratch (no allocations allowed) ----------------
__device__ float g_xn[(size_t)Bb * NSEQ * DIMV];
__device__ float g_q[(size_t)BHn * NSEQ * DHd];
__device__ float g_k[(size_t)BHn * NSEQ * DHd];
__device__ float g_v[(size_t)BHn * NSEQ * DHd];
__device__ float g_ql[BHn * MLM * DHd];
__device__ float g_kl[BHn * MLM * DHd];
__device__ float g_attn2[BHn * MLM * MLM];
__device__ float g_Y[BHn * MLM * MLM];
__device__ float g_P[BHn * MLM * MLM];
__device__ float g_Qm[BHn * MLM * MLM];
__device__ float g_Za[BHn * MLM * MLM];
__device__ float g_Zb[BHn * MLM * MLM];
__device__ float g_W2[BHn * MLM * DHd];
__device__ float g_W3[BHn * MLM * DHd];
__device__ float g_Wpart[(size_t)BHn * NCHUNK * MLM * DHd];
__device__ float g_Spart[BHn * NCHUNK * MLM];
__device__ float g_outpre[(size_t)Bb * NSEQ * DIMV];
__device__ int   g_maxc_bits;

// ---------------- reset (atomics target must be re-zeroed every call) ----------
__global__ void reset_kernel() { g_maxc_bits = 0; }

// ---------------- layernorm: x[16384,512] -> g_xn ------------------------------
__global__ __launch_bounds__(128) void ln_kernel(const float* __restrict__ x,
                                                 const float* __restrict__ gam,
                                                 const float* __restrict__ bet) {
    int row = blockIdx.x;
    int tid = threadIdx.x;
    float4 v = ((const float4*)x)[(size_t)row * 128 + tid];
    float s1 = v.x + v.y + v.z + v.w;
    float s2 = v.x * v.x + v.y * v.y + v.z * v.z + v.w * v.w;
#pragma unroll
    for (int o = 16; o; o >>= 1) {
        s1 += __shfl_xor_sync(0xffffffffu, s1, o);
        s2 += __shfl_xor_sync(0xffffffffu, s2, o);
    }
    __shared__ float r1[4], r2[4];
    int w = tid >> 5;
    if ((tid & 31) == 0) { r1[w] = s1; r2[w] = s2; }
    __syncthreads();
    s1 = r1[0] + r1[1] + r1[2] + r1[3];
    s2 = r2[0] + r2[1] + r2[2] + r2[3];
    float mean = s1 * (1.f / 512.f);
    float var  = s2 * (1.f / 512.f) - mean * mean;
    float rstd = rsqrtf(var + 1e-5f);
    float4 g4 = ((const float4*)gam)[tid];
    float4 b4 = ((const float4*)bet)[tid];
    float4 o;
    o.x = (v.x - mean) * rstd * g4.x + b4.x;
    o.y = (v.y - mean) * rstd * g4.y + b4.y;
    o.z = (v.z - mean) * rstd * g4.z + b4.z;
    o.w = (v.w - mean) * rstd * g4.w + b4.w;
    ((float4*)g_xn)[(size_t)row * 128 + tid] = o;
}

// ---------------- qkv GEMM: g_xn[16384,512] @ Wqkv[512,1536] -> q,k,v heads -----
__global__ __launch_bounds__(256) void sgemm_qkv_kernel(const float* __restrict__ Bm) {
    __shared__ float As[8][128];
    __shared__ float Bs[8][128];
    int tid = threadIdx.x;
    int ty = tid >> 4, tx = tid & 15;
    int rowBase = blockIdx.y * 128;
    int colBase = blockIdx.x * 128;
    int arow = tid >> 1, acol = (tid & 1) * 4;
    int brow = tid >> 5, bcol = (tid & 31) * 4;
    float acc[8][8];
#pragma unroll
    for (int i = 0; i < 8; i++)
#pragma unroll
        for (int j = 0; j < 8; j++) acc[i][j] = 0.f;

    for (int k0 = 0; k0 < 512; k0 += 8) {
        float4 av = *(const float4*)&g_xn[(size_t)(rowBase + arow) * 512 + k0 + acol];
        As[acol + 0][arow] = av.x; As[acol + 1][arow] = av.y;
        As[acol + 2][arow] = av.z; As[acol + 3][arow] = av.w;
        float4 bv = *(const float4*)&Bm[(size_t)(k0 + brow) * 1536 + colBase + bcol];
        *(float4*)&Bs[brow][bcol] = bv;
        __syncthreads();
#pragma unroll
        for (int kk = 0; kk < 8; kk++) {
            float a[8], b[8];
            *(float4*)a       = *(const float4*)&As[kk][ty * 8];
            *(float4*)(a + 4) = *(const float4*)&As[kk][ty * 8 + 4];
            *(float4*)b       = *(const float4*)&Bs[kk][tx * 8];
            *(float4*)(b + 4) = *(const float4*)&Bs[kk][tx * 8 + 4];
#pragma unroll
            for (int i = 0; i < 8; i++)
#pragma unroll
                for (int j = 0; j < 8; j++) acc[i][j] += a[i] * b[j];
        }
        __syncthreads();
    }
#pragma unroll
    for (int i = 0; i < 8; i++) {
        int gr = rowBase + ty * 8 + i;
        int bb = gr >> 13;
        int n  = gr & 8191;
#pragma unroll
        for (int jb = 0; jb < 8; jb += 4) {
            int gc = colBase + tx * 8 + jb;
            int sec = gc >> 9;
            int h = (gc >> 6) & 7;
            int d = gc & 63;
            float4 o = make_float4(acc[i][jb], acc[i][jb + 1], acc[i][jb + 2], acc[i][jb + 3]);
            float* dst;
            if (sec == 0) {
                o.x *= SCALE; o.y *= SCALE; o.z *= SCALE; o.w *= SCALE;
                dst = g_q;
            } else if (sec == 1) dst = g_k;
            else dst = g_v;
            *(float4*)&dst[((size_t)(bb * 8 + h) * NSEQ + n) * DHd + d] = o;
        }
    }
}

// ---------------- landmarks: mean over groups of 32 ----------------------------
__global__ void landmark_kernel() {
    int idx = blockIdx.x * 256 + threadIdx.x;   // 0 .. 2*16*256*64-1
    int sel = idx >> 18;
    int r = idx & 262143;
    int bh = r >> 14;
    int m = (r >> 6) & 255;
    int d = r & 63;
    const float* src = sel ? g_k : g_q;
    const float* p = src + ((size_t)bh * NSEQ + m * LGRP) * DHd + d;
    float s = 0.f;
#pragma unroll
    for (int i = 0; i < LGRP; i++) s += p[i * DHd];
    (sel ? g_kl : g_ql)[(bh * MLM + m) * DHd + d] = s * (1.f / LGRP);
}

// ---------------- attn2 = softmax(q_l k_l^T), per bh [256,256] ------------------
__global__ __launch_bounds__(256) void attn2_kernel() {
    int bh = blockIdx.x;
    int m = threadIdx.x;
    __shared__ float4 kls[1024];
    float4 q[16];
    const float4* qp = (const float4*)g_ql + (size_t)(bh * MLM + m) * 16;
#pragma unroll
    for (int i = 0; i < 16; i++) q[i] = qp[i];
    float sum = 0.f;
    float* arow = g_attn2 + (size_t)bh * 65536 + (size_t)m * 256;
    for (int tile = 0; tile < 4; tile++) {
        __syncthreads();
        const float4* src = (const float4*)g_kl + (size_t)(bh * MLM + tile * 64) * 16;
#pragma unroll
        for (int i = 0; i < 4; i++) kls[threadIdx.x + i * 256] = src[threadIdx.x + i * 256];
        __syncthreads();
        for (int j = 0; j < 64; j++) {
            const float4* kr = &kls[j * 16];
            float s = 0.f;
#pragma unroll
            for (int d = 0; d < 16; d++) {
                float4 a = q[d], b = kr[d];
                s += a.x * b.x + a.y * b.y + a.z * b.z + a.w * b.w;
            }
            float p = __expf(s);
            sum += p;
            arow[tile * 64 + j] = p;
        }
    }
    float inv = 1.f / sum;
    for (int j = 0; j < 256; j++) arow[j] *= inv;
}

// ---------------- global max column-sum of attn2 --------------------------------
__global__ __launch_bounds__(256) void colmax_kernel() {
    int bh = blockIdx.x;
    int j = threadIdx.x;
    const float* a = g_attn2 + (size_t)bh * 65536;
    float s = 0.f;
    for (int m2 = 0; m2 < 256; m2++) s += a[m2 * 256 + j];
    __shared__ float red[256];
    red[j] = s;
    __syncthreads();
    for (int o = 128; o; o >>= 1) {
        if (j < o) red[j] = fmaxf(red[j], red[j + o]);
        __syncthreads();
    }
    if (j == 0) atomicMax(&g_maxc_bits, __float_as_int(red[0]));
}

// ---------------- z0 = attn2^T / maxcolsum  (rowsums of softmax == 1) -----------
__global__ void z0_kernel() {
    int idx = blockIdx.x * 256 + threadIdx.x;
    int bh = idx >> 16;
    int i = (idx >> 8) & 255;
    int j = idx & 255;
    float scale = 1.f / __int_as_float(g_maxc_bits);
    g_Za[idx] = g_attn2[(bh << 16) + (j << 8) + i] * scale;
}

// ---------------- batched per-bh GEMM: C = alpha * A @ (beta*I + sgn*B) ---------
__device__ __forceinline__ float* pickBuf(int id) {
    switch (id) {
        case 0: return g_attn2;
        case 1: return g_Y;
        case 2: return g_P;
        case 3: return g_Qm;
        case 4: return g_Za;
        case 5: return g_Zb;
        case 6: return g_W2;
        default: return g_W3;
    }
}

__global__ __launch_bounds__(256) void gemm_bh_kernel(int cId, int aId, int bId, int Nn,
                                                      float beta, float sgn, float alpha) {
    int bh = blockIdx.z, mt = blockIdx.y, nt = blockIdx.x;
    const float* A  = pickBuf(aId) + (size_t)bh * 65536;
    const float* Bp = pickBuf(bId) + (size_t)bh * 256 * Nn;
    float*       C  = pickBuf(cId) + (size_t)bh * 256 * Nn;
    __shared__ float As[16][64];
    __shared__ float Bs[16][64];
    int tid = threadIdx.x;
    int ar = tid >> 2, ac = (tid & 3) * 4;
    int br = tid >> 4, bc = (tid & 15) * 4;
    int ty = tid >> 4, tx = tid & 15;
    float acc[4][4];
#pragma unroll
    for (int i = 0; i < 4; i++)
#pragma unroll
        for (int j = 0; j < 4; j++) acc[i][j] = 0.f;

    for (int k0 = 0; k0 < 256; k0 += 16) {
        float4 av = *(const float4*)&A[(size_t)(mt * 64 + ar) * 256 + k0 + ac];
        As[ac + 0][ar] = av.x; As[ac + 1][ar] = av.y;
        As[ac + 2][ar] = av.z; As[ac + 3][ar] = av.w;
        int gk = k0 + br;
        int gc = nt * 64 + bc;
        float4 bv = *(const float4*)&Bp[(size_t)gk * Nn + gc];
        bv.x = sgn * bv.x + (gk == gc + 0 ? beta : 0.f);
        bv.y = sgn * bv.y + (gk == gc + 1 ? beta : 0.f);
        bv.z = sgn * bv.z + (gk == gc + 2 ? beta : 0.f);
        bv.w = sgn * bv.w + (gk == gc + 3 ? beta : 0.f);
        *(float4*)&Bs[br][bc] = bv;
        __syncthreads();
#pragma unroll
        for (int kk = 0; kk < 16; kk++) {
            float4 a4 = *(const float4*)&As[kk][ty * 4];
            float4 b4 = *(const float4*)&Bs[kk][tx * 4];
            acc[0][0] += a4.x * b4.x; acc[0][1] += a4.x * b4.y; acc[0][2] += a4.x * b4.z; acc[0][3] += a4.x * b4.w;
            acc[1][0] += a4.y * b4.x; acc[1][1] += a4.y * b4.y; acc[1][2] += a4.y * b4.z; acc[1][3] += a4.y * b4.w;
            acc[2][0] += a4.z * b4.x; acc[2][1] += a4.z * b4.y; acc[2][2] += a4.z * b4.z; acc[2][3] += a4.z * b4.w;
            acc[3][0] += a4.w * b4.x; acc[3][1] += a4.w * b4.y; acc[3][2] += a4.w * b4.z; acc[3][3] += a4.w * b4.w;
        }
        __syncthreads();
    }
#pragma unroll
    for (int i = 0; i < 4; i++) {
        float4 o = make_float4(acc[i][0] * alpha, acc[i][1] * alpha,
                               acc[i][2] * alpha, acc[i][3] * alpha);
        *(float4*)&C[(size_t)(mt * 64 + ty * 4 + i) * Nn + nt * 64 + tx * 4] = o;
    }
}

// ---------------- W2 = softmax(q_l k^T) @ v  (split-K, no max needed) ----------
__global__ __launch_bounds__(256) void flash_w2_kernel() {
    int chunk = blockIdx.x, bh = blockIdx.y;
    int tid = threadIdx.x;  // = landmark row m
    __shared__ float4 ks[512], vs[512];
    float4 q[16];
    const float4* qp = (const float4*)g_ql + (size_t)(bh * MLM + tid) * 16;
#pragma unroll
    for (int i = 0; i < 16; i++) q[i] = qp[i];
    float4 acc[16];
#pragma unroll
    for (int i = 0; i < 16; i++) acc[i] = make_float4(0.f, 0.f, 0.f, 0.f);
    float sum = 0.f;

    for (int t = 0; t < 8; t++) {
        int k0 = chunk * 256 + t * 32;
        __syncthreads();
        const float4* kp = (const float4*)g_k + ((size_t)bh * NSEQ + k0) * 16;
        const float4* vp = (const float4*)g_v + ((size_t)bh * NSEQ + k0) * 16;
        ks[tid] = kp[tid]; ks[tid + 256] = kp[tid + 256];
        vs[tid] = vp[tid]; vs[tid + 256] = vp[tid + 256];
        __syncthreads();
        for (int j = 0; j < 32; j++) {
            float s = 0.f;
#pragma unroll
            for (int d = 0; d < 16; d++) {
                float4 a = q[d], b = ks[j * 16 + d];
                s += a.x * b.x + a.y * b.y + a.z * b.z + a.w * b.w;
            }
            float p = __expf(s);
            sum += p;
#pragma unroll
            for (int d = 0; d < 16; d++) {
                float4 b = vs[j * 16 + d];
                acc[d].x += p * b.x; acc[d].y += p * b.y;
                acc[d].z += p * b.z; acc[d].w += p * b.w;
            }
        }
    }
    float4* wp = (float4*)(g_Wpart + (size_t)((bh * NCHUNK + chunk) * MLM + tid) * DHd);
#pragma unroll
    for (int d = 0; d < 16; d++) wp[d] = acc[d];
    g_Spart[(bh * NCHUNK + chunk) * MLM + tid] = sum;
}

__global__ void combine_w2_kernel() {
    int idx = blockIdx.x * 256 + threadIdx.x;  // 16*256*64
    int bh = idx >> 14;
    int m = (idx >> 6) & 255;
    int d = idx & 63;
    float num = 0.f, den = 0.f;
    for (int c = 0; c < NCHUNK; c++) {
        num += g_Wpart[(size_t)((bh * NCHUNK + c) * MLM + m) * DHd + d];
        den += g_Spart[(bh * NCHUNK + c) * MLM + m];
    }
    g_W2[(bh * MLM + m) * DHd + d] = num / den;
}

// ---------------- fused: softmax(q k_l^T) @ W3  + conv residual -> out_pre ------
__global__ __launch_bounds__(256) void attn1_conv_kernel(const float* __restrict__ convw) {
    int rt = blockIdx.x, bh = blockIdx.y;
    int tid = threadIdx.x;
    int n = rt * 256 + tid;
    int h = bh & 7;
    __shared__ float4 kls[1024];
    __shared__ float4 w3s[1024];
    __shared__ float cw[KSZ];
    if (tid < KSZ) cw[tid] = convw[h * KSZ + tid];

    float4 q[16];
    const float4* qp = (const float4*)g_q + ((size_t)bh * NSEQ + n) * 16;
#pragma unroll
    for (int i = 0; i < 16; i++) q[i] = qp[i];
    float4 acc[16];
#pragma unroll
    for (int i = 0; i < 16; i++) acc[i] = make_float4(0.f, 0.f, 0.f, 0.f);
    float sum = 0.f;

    for (int tile = 0; tile < 4; tile++) {
        __syncthreads();
        const float4* kp = (const float4*)g_kl + (size_t)(bh * MLM + tile * 64) * 16;
        const float4* wp = (const float4*)g_W3 + (size_t)(bh * MLM + tile * 64) * 16;
#pragma unroll
        for (int i = 0; i < 4; i++) {
            kls[tid + i * 256] = kp[tid + i * 256];
            w3s[tid + i * 256] = wp[tid + i * 256];
        }
        __syncthreads();
        for (int j = 0; j < 64; j++) {
            float s = 0.f;
#pragma unroll
            for (int d = 0; d < 16; d++) {
                float4 a = q[d], b = kls[j * 16 + d];
                s += a.x * b.x + a.y * b.y + a.z * b.z + a.w * b.w;
            }
            float p = __expf(s);
            sum += p;
#pragma unroll
            for (int d = 0; d < 16; d++) {
                float4 b = w3s[j * 16 + d];
                acc[d].x += p * b.x; acc[d].y += p * b.y;
                acc[d].z += p * b.z; acc[d].w += p * b.w;
            }
        }
    }
    float inv = 1.f / sum;
#pragma unroll
    for (int d = 0; d < 16; d++) {
        acc[d].x *= inv; acc[d].y *= inv; acc[d].z *= inv; acc[d].w *= inv;
    }
    // depthwise conv-33 residual on v (same head), zero padded
    const float4* vb = (const float4*)g_v + (size_t)bh * NSEQ * 16;
#pragma unroll
    for (int t = 0; t < KSZ; t++) {
        int r = n + t - PADc;
        if ((unsigned)r < (unsigned)NSEQ) {
            float w = cw[t];
            const float4* vr = vb + (size_t)r * 16;
#pragma unroll
            for (int d = 0; d < 16; d++) {
                float4 b = vr[d];
                acc[d].x += w * b.x; acc[d].y += w * b.y;
                acc[d].z += w * b.z; acc[d].w += w * b.w;
            }
        }
    }
    int bb = bh >> 3;
    float4* op = (float4*)(g_outpre + (size_t)(bb * NSEQ + n) * DIMV + h * DHd);
#pragma unroll
    for (int d = 0; d < 16; d++) op[d] = acc[d];
}

// ---------------- final GEMM: out = xn + out_pre @ W_out + b_out ----------------
__global__ __launch_bounds__(256) void sgemm_out_kernel(const float* __restrict__ Bm,
                                                        const float* __restrict__ bout,
                                                        float* __restrict__ out) {
    __shared__ float As[8][128];
    __shared__ float Bs[8][128];
    int tid = threadIdx.x;
    int ty = tid >> 4, tx = tid & 15;
    int rowBase = blockIdx.y * 128;
    int colBase = blockIdx.x * 128;
    int arow = tid >> 1, acol = (tid & 1) * 4;
    int brow = tid >> 5, bcol = (tid & 31) * 4;
    float acc[8][8];
#pragma unroll
    for (int i = 0; i < 8; i++)
#pragma unroll
        for (int j = 0; j < 8; j++) acc[i][j] = 0.f;

    for (int k0 = 0; k0 < 512; k0 += 8) {
        float4 av = *(const float4*)&g_outpre[(size_t)(rowBase + arow) * 512 + k0 + acol];
        As[acol + 0][arow] = av.x; As[acol + 1][arow] = av.y;
        As[acol + 2][arow] = av.z; As[acol + 3][arow] = av.w;
        float4 bv = *(const float4*)&Bm[(size_t)(k0 + brow) * 512 + colBase + bcol];
        *(float4*)&Bs[brow][bcol] = bv;
        __syncthreads();
#pragma unroll
        for (int kk = 0; kk < 8; kk++) {
            float a[8], b[8];
            *(float4*)a       = *(const float4*)&As[kk][ty * 8];
            *(float4*)(a + 4) = *(const float4*)&As[kk][ty * 8 + 4];
            *(float4*)b       = *(const float4*)&Bs[kk][tx * 8];
            *(float4*)(b + 4) = *(const float4*)&Bs[kk][tx * 8 + 4];
#pragma unroll
            for (int i = 0; i < 8; i++)
#pragma unroll
                for (int j = 0; j < 8; j++) acc[i][j] += a[i] * b[j];
        }
        __syncthreads();
    }
#pragma unroll
    for (int i = 0; i < 8; i++) {
        int gr = rowBase + ty * 8 + i;
#pragma unroll
        for (int jb = 0; jb < 8; jb += 4) {
            int gc = colBase + tx * 8 + jb;
            float4 bo = *(const float4*)&bout[gc];
            float4 xv = *(const float4*)&g_xn[(size_t)gr * 512 + gc];
            float4 o = make_float4(acc[i][jb] + bo.x + xv.x,
                                   acc[i][jb + 1] + bo.y + xv.y,
                                   acc[i][jb + 2] + bo.z + xv.z,
                                   acc[i][jb + 3] + bo.w + xv.w);
            *(float4*)&out[(size_t)gr * 512 + gc] = o;
        }
    }
}

// ---------------- host launcher --------------------------------------------------
extern "C" void kernel_launch(void* const* d_in, const int* in_sizes, int n_in,
                              void* d_out, int out_size) {
    const float* x     = (const float*)d_in[0];
    const float* ln_g  = (const float*)d_in[1];
    const float* ln_b  = (const float*)d_in[2];
    const float* W_qkv = (const float*)d_in[3];
    const float* W_out = (const float*)d_in[4];
    const float* b_out = (const float*)d_in[5];
    const float* convw = (const float*)d_in[6];
    float* out = (float*)d_out;

    reset_kernel<<<1, 1>>>();
    ln_kernel<<<Bb * NSEQ, 128>>>(x, ln_g, ln_b);
    sgemm_qkv_kernel<<<dim3(12, 128), 256>>>(W_qkv);
    landmark_kernel<<<2048, 256>>>();
    attn2_kernel<<<16, 256>>>();
    colmax_kernel<<<16, 256>>>();
    z0_kernel<<<4096, 256>>>();

    int zc = 4, zn = 5;  // Za, Zb
    for (int it = 0; it < 6; it++) {
        gemm_bh_kernel<<<dim3(4, 4, 16), 256>>>(1, 0, zc, 256, 0.f, 1.f, 1.f);     // Y  = A2 @ Z
        gemm_bh_kernel<<<dim3(4, 4, 16), 256>>>(2, 1, 1, 256, 7.f, -1.f, 1.f);     // P  = Y @ (7I - Y)
        gemm_bh_kernel<<<dim3(4, 4, 16), 256>>>(3, 1, 2, 256, 15.f, -1.f, 1.f);    // Qm = Y @ (15I - P)
        gemm_bh_kernel<<<dim3(4, 4, 16), 256>>>(zn, zc, 3, 256, 13.f, -1.f, 0.25f);// Z' = 0.25 Z @ (13I - Qm)
        int t = zc; zc = zn; zn = t;
    }

    flash_w2_kernel<<<dim3(NCHUNK, 16), 256>>>();
    combine_w2_kernel<<<1024, 256>>>();
    gemm_bh_kernel<<<dim3(1, 4, 16), 256>>>(7, zc, 6, 64, 0.f, 1.f, 1.f);          // W3 = Z @ W2
    attn1_conv_kernel<<<dim3(32, 16), 256>>>(convw);
    sgemm_out_kernel<<<dim3(4, 128), 256>>>(W_out, b_out, out);
}